// round 15
// baseline (speedup 1.0000x reference)
#include <cuda_runtime.h>
#include <math_constants.h>

// SpatialAttention: out = x * hardsigmoid(conv3x3([mean_c(x); max_c(x)]))
// x: [16, 256, 128, 128] fp32, conv_w: [1, 2, 3, 3] fp32.
//
// Two-stream pipeline + ONE-LOAD-PER-THREAD reduce.
// Evidence across 7 variants: any reduce looping over strided loads caps at
// ~2.4 TB/s regardless of blocks/threads/occupancy; mul's one-load-per-
// thread shape runs 4.3-6.6 TB/s (block churn supplies the MLP that ptxas
// denies looping threads). So reduce now = 4096 blocks/chunk, each thread
// loads exactly ONE float4; 3-stage smem fold over 8 channels -> partial.

#define BATCH 16
#define CH    256
#define HH    128
#define WW    128
#define HWSZ  (HH * WW)          // 16384
#define HW4   (HWSZ / 4)         // 4096 float4 cols per (b,c) plane
#define NCHNK 16                 // 1 batch per chunk (16 MiB x-slice)

#define SEG   32                 // channel segments (8 channels each)

#define R_BLK 4096               // reduce blocks per chunk (32 cblk x 128 strips)
#define C_BLK 64                 // conv blocks per chunk
#define M_BLK 4096               // mul blocks per chunk

__device__ float g_pavg[SEG][BATCH * HWSZ];   // per-seg partial sums  (32 MB)
__device__ float g_pmax[SEG][BATCH * HWSZ];   // per-seg partial maxes (32 MB)
__device__ float g_att[BATCH * HWSZ];

// ---------------------------------------------------------------------------
// reduce: block = (8 channels x 32 float4 cols). Thread loads ONE float4,
// 3-stage smem fold over channels, 32 partial float4 stores per block.
// ---------------------------------------------------------------------------
__global__ void __launch_bounds__(256) reduce_kernel(const float* __restrict__ x, int b) {
    __shared__ float4 ssum[256];
    __shared__ float4 smax[256];

    int t     = threadIdx.x;
    int col_l = t & 31;
    int cg    = t >> 5;                    // 0..7 channel within block
    int strip = blockIdx.x & 127;          // 0..127 column strip
    int cblk  = blockIdx.x >> 7;           // 0..31 channel block (= seg)
    int col   = strip * 32 + col_l;
    int ch    = cblk * 8 + cg;

    float4 v = reinterpret_cast<const float4*>(x)
                   [(size_t)b * CH * HW4 + (size_t)ch * HW4 + col];  // ONE load

    ssum[t] = v; smax[t] = v;
    __syncthreads();

    #pragma unroll
    for (int off = 128; off >= 32; off >>= 1) {
        if (t < off) {
            float4 s2 = ssum[t + off], m2 = smax[t + off];
            float4 sa = ssum[t],       ma = smax[t];
            sa.x += s2.x; sa.y += s2.y; sa.z += s2.z; sa.w += s2.w;
            ma.x = fmaxf(ma.x, m2.x); ma.y = fmaxf(ma.y, m2.y);
            ma.z = fmaxf(ma.z, m2.z); ma.w = fmaxf(ma.w, m2.w);
            ssum[t] = sa; smax[t] = ma;
        }
        __syncthreads();
    }

    if (t < 32) {
        reinterpret_cast<float4*>(g_pavg[cblk])[b * HW4 + strip * 32 + t] = ssum[t];
        reinterpret_cast<float4*>(g_pmax[cblk])[b * HW4 + strip * 32 + t] = smax[t];
    }
}

// ---------------------------------------------------------------------------
// conv: block = 2 rows (256 positions). Fold 32 partials into smem for the
// 4 needed rows (2 + halo), then 3x3 conv + hardsigmoid from smem.
// ---------------------------------------------------------------------------
__global__ void __launch_bounds__(256) conv_kernel(const float* __restrict__ wt, int b) {
    __shared__ float sA[4 * WW];
    __shared__ float sM[4 * WW];

    int bk   = blockIdx.x;            // rows 2bk..2bk+1
    int row0 = 2 * bk - 1;
    int t    = threadIdx.x;

    const float inv = 1.0f / (float)CH;

    #pragma unroll
    for (int j = t; j < 4 * WW; j += 256) {
        int gh = row0 + (j >> 7);
        float av = 0.f, mx = -CUDART_INF_F;
        if (gh >= 0 && gh < HH) {
            int o = b * HWSZ + gh * WW + (j & (WW - 1));
            #pragma unroll
            for (int sgi = 0; sgi < SEG; sgi++) {
                av += __ldg(&g_pavg[sgi][o]);
                mx  = fmaxf(mx, __ldg(&g_pmax[sgi][o]));
            }
            av *= inv;
        }
        sA[j] = av; sM[j] = mx;
    }
    __syncthreads();

    int h  = 2 * bk + (t >> 7);
    int w  = t & (WW - 1);
    int lr = (t >> 7) + 1;

    float acc = 0.f;
    #pragma unroll
    for (int kh = 0; kh < 3; kh++) {
        int hh = h + kh - 1;
        if (hh < 0 || hh >= HH) continue;
        int lrow = lr + kh - 1;
        #pragma unroll
        for (int kw = 0; kw < 3; kw++) {
            int ww = w + kw - 1;
            if (ww < 0 || ww >= WW) continue;
            int o = lrow * WW + ww;
            acc += __ldg(&wt[kh * 3 + kw])     * sA[o]
                 + __ldg(&wt[9 + kh * 3 + kw]) * sM[o];
        }
    }
    float y = fminf(fmaxf(acc + 3.0f, 0.0f), 6.0f) * (1.0f / 6.0f);
    g_att[b * HWSZ + h * WW + w] = y;
}

// ---------------------------------------------------------------------------
__global__ void __launch_bounds__(256) mul_kernel(const float* __restrict__ x,
                                                  float* __restrict__ out, int b) {
    int idx = blockIdx.x * 256 + threadIdx.x;   // 0 .. CH*HW4-1
    int col = idx & (HW4 - 1);

    size_t gidx = (size_t)b * CH * HW4 + idx;

    float4 v = __ldcs(reinterpret_cast<const float4*>(x) + gidx);
    float4 a = __ldg(reinterpret_cast<const float4*>(g_att) + (size_t)b * HW4 + col);

    v.x *= a.x; v.y *= a.y; v.z *= a.z; v.w *= a.w;
    __stcs(reinterpret_cast<float4*>(out) + gidx, v);
}

// ---------------------------------------------------------------------------
extern "C" void kernel_launch(void* const* d_in, const int* in_sizes, int n_in,
                              void* d_out, int out_size) {
    const float* x  = (const float*)d_in[0];
    const float* wt = (const float*)d_in[1];
    float* out      = (float*)d_out;

    static cudaStream_t sB = []() {
        cudaStream_t s;
        cudaStreamCreateWithFlags(&s, cudaStreamNonBlocking);
        return s;
    }();
    static cudaEvent_t evFork = []() {
        cudaEvent_t e;
        cudaEventCreateWithFlags(&e, cudaEventDisableTiming);
        return e;
    }();
    static cudaEvent_t evJoin = []() {
        cudaEvent_t e;
        cudaEventCreateWithFlags(&e, cudaEventDisableTiming);
        return e;
    }();

    // Fork second stream into the captured graph.
    cudaEventRecord(evFork, 0);
    cudaStreamWaitEvent(sB, evFork, 0);

    // Even chunks on capture stream, odd chunks on sB.
    for (int b = 0; b < NCHNK; b++) {
        cudaStream_t s = (b & 1) ? sB : (cudaStream_t)0;
        reduce_kernel<<<R_BLK, 256, 0, s>>>(x, b);
        conv_kernel<<<C_BLK, 256, 0, s>>>(wt, b);
        mul_kernel<<<M_BLK, 256, 0, s>>>(x, out, b);
    }

    // Join.
    cudaEventRecord(evJoin, sB);
    cudaStreamWaitEvent(0, evJoin, 0);
}

// round 16
// speedup vs baseline: 1.4291x; 1.4291x over previous
#include <cuda_runtime.h>
#include <math_constants.h>

// SpatialAttention: out = x * hardsigmoid(conv3x3([mean_c(x); max_c(x)]))
// x: [16, 256, 128, 128] fp32, conv_w: [1, 2, 3, 3] fp32.
//
// Two-stream pipeline + cp.async-staged reduce.
// Register loops cap at MLP~2 (R12) and smem-fold blocks drown in shared
// traffic (R15). cp.async gives EXPLICIT pipeline depth: 8 waves x 4
// channels staged into a 32KB double buffer; accumulate wave w-1 while
// wave w is in flight. Threads read only their own staged data -> no
// barriers. SEG=8 partials (1 MB/batch) folded by conv.

#define BATCH 16
#define CH    256
#define HH    128
#define WW    128
#define HWSZ  (HH * WW)          // 16384
#define HW4   (HWSZ / 4)         // 4096 float4 cols per (b,c) plane
#define NCHNK 16                 // 1 batch per chunk (16 MiB x-slice)

#define SEG    8                 // channel segments (32 ch each)
#define CPW    4                 // channels per wave
#define WAVES  8                 // 32 channels / 4

#define R_BLK (SEG * 16)         // 128 reduce blocks per chunk (16 strips)
#define C_BLK 64                 // conv blocks per chunk
#define M_BLK 4096               // mul blocks per chunk

__device__ float g_pavg[SEG][BATCH * HWSZ];   // per-seg partial sums
__device__ float g_pmax[SEG][BATCH * HWSZ];   // per-seg partial maxes
__device__ float g_att[BATCH * HWSZ];

// ---------------------------------------------------------------------------
// reduce: block = (seg, strip of 256 float4 cols). 32 channels in 8 waves of
// 4 via cp.async.cg (16B), double-buffered. No __syncthreads anywhere.
// ---------------------------------------------------------------------------
__global__ void __launch_bounds__(256) reduce_kernel(const float* __restrict__ x, int b) {
    __shared__ float4 stage[2][CPW][256];    // 32 KB

    int t     = threadIdx.x;
    int strip = blockIdx.x & 15;             // 0..15
    int seg   = blockIdx.x >> 4;             // 0..7
    int col   = strip * 256 + t;

    const float4* xp = reinterpret_cast<const float4*>(x)
                     + (size_t)b * CH * HW4 + (size_t)(seg * 32) * HW4 + col;

    unsigned sbase[2];
    sbase[0] = (unsigned)__cvta_generic_to_shared(&stage[0][0][t]);
    sbase[1] = (unsigned)__cvta_generic_to_shared(&stage[1][0][t]);
    const unsigned srow = 256 * sizeof(float4);   // stride between channels

    float4 s = make_float4(0.f, 0.f, 0.f, 0.f);
    float4 m = make_float4(-CUDART_INF_F, -CUDART_INF_F, -CUDART_INF_F, -CUDART_INF_F);

    // Prologue: issue wave 0.
    #pragma unroll
    for (int j = 0; j < CPW; j++) {
        asm volatile("cp.async.cg.shared.global [%0], [%1], 16;"
                     :: "r"(sbase[0] + j * srow), "l"(xp + j * HW4));
    }
    asm volatile("cp.async.commit_group;" ::: "memory");

    #pragma unroll
    for (int w = 1; w < WAVES; w++) {
        // Issue wave w into buffer w&1.
        const float4* xw = xp + (size_t)(w * CPW) * HW4;
        #pragma unroll
        for (int j = 0; j < CPW; j++) {
            asm volatile("cp.async.cg.shared.global [%0], [%1], 16;"
                         :: "r"(sbase[w & 1] + j * srow), "l"(xw + j * HW4));
        }
        asm volatile("cp.async.commit_group;" ::: "memory");

        // Wait for wave w-1 (all but the newest group), accumulate it.
        asm volatile("cp.async.wait_group 1;" ::: "memory");
        #pragma unroll
        for (int j = 0; j < CPW; j++) {
            float4 v = stage[(w - 1) & 1][j][t];
            s.x += v.x; s.y += v.y; s.z += v.z; s.w += v.w;
            m.x = fmaxf(m.x, v.x); m.y = fmaxf(m.y, v.y);
            m.z = fmaxf(m.z, v.z); m.w = fmaxf(m.w, v.w);
        }
    }

    // Epilogue: last wave.
    asm volatile("cp.async.wait_group 0;" ::: "memory");
    #pragma unroll
    for (int j = 0; j < CPW; j++) {
        float4 v = stage[(WAVES - 1) & 1][j][t];
        s.x += v.x; s.y += v.y; s.z += v.z; s.w += v.w;
        m.x = fmaxf(m.x, v.x); m.y = fmaxf(m.y, v.y);
        m.z = fmaxf(m.z, v.z); m.w = fmaxf(m.w, v.w);
    }

    reinterpret_cast<float4*>(g_pavg[seg])[b * HW4 + col] = s;
    reinterpret_cast<float4*>(g_pmax[seg])[b * HW4 + col] = m;
}

// ---------------------------------------------------------------------------
// conv: block = 2 rows (256 positions). Fold 8 partials into smem for the
// 4 needed rows (2 + halo), then 3x3 conv + hardsigmoid from smem.
// ---------------------------------------------------------------------------
__global__ void __launch_bounds__(256) conv_kernel(const float* __restrict__ wt, int b) {
    __shared__ float sA[4 * WW];
    __shared__ float sM[4 * WW];

    int bk   = blockIdx.x;            // rows 2bk..2bk+1
    int row0 = 2 * bk - 1;
    int t    = threadIdx.x;

    const float inv = 1.0f / (float)CH;

    #pragma unroll
    for (int j = t; j < 4 * WW; j += 256) {
        int gh = row0 + (j >> 7);
        float av = 0.f, mx = -CUDART_INF_F;
        if (gh >= 0 && gh < HH) {
            int o = b * HWSZ + gh * WW + (j & (WW - 1));
            #pragma unroll
            for (int sgi = 0; sgi < SEG; sgi++) {
                av += __ldg(&g_pavg[sgi][o]);
                mx  = fmaxf(mx, __ldg(&g_pmax[sgi][o]));
            }
            av *= inv;
        }
        sA[j] = av; sM[j] = mx;
    }
    __syncthreads();

    int h  = 2 * bk + (t >> 7);
    int w  = t & (WW - 1);
    int lr = (t >> 7) + 1;

    float acc = 0.f;
    #pragma unroll
    for (int kh = 0; kh < 3; kh++) {
        int hh = h + kh - 1;
        if (hh < 0 || hh >= HH) continue;
        int lrow = lr + kh - 1;
        #pragma unroll
        for (int kw = 0; kw < 3; kw++) {
            int ww = w + kw - 1;
            if (ww < 0 || ww >= WW) continue;
            int o = lrow * WW + ww;
            acc += __ldg(&wt[kh * 3 + kw])     * sA[o]
                 + __ldg(&wt[9 + kh * 3 + kw]) * sM[o];
        }
    }
    float y = fminf(fmaxf(acc + 3.0f, 0.0f), 6.0f) * (1.0f / 6.0f);
    g_att[b * HWSZ + h * WW + w] = y;
}

// ---------------------------------------------------------------------------
__global__ void __launch_bounds__(256) mul_kernel(const float* __restrict__ x,
                                                  float* __restrict__ out, int b) {
    int idx = blockIdx.x * 256 + threadIdx.x;   // 0 .. CH*HW4-1
    int col = idx & (HW4 - 1);

    size_t gidx = (size_t)b * CH * HW4 + idx;

    float4 v = __ldcs(reinterpret_cast<const float4*>(x) + gidx);
    float4 a = __ldg(reinterpret_cast<const float4*>(g_att) + (size_t)b * HW4 + col);

    v.x *= a.x; v.y *= a.y; v.z *= a.z; v.w *= a.w;
    __stcs(reinterpret_cast<float4*>(out) + gidx, v);
}

// ---------------------------------------------------------------------------
extern "C" void kernel_launch(void* const* d_in, const int* in_sizes, int n_in,
                              void* d_out, int out_size) {
    const float* x  = (const float*)d_in[0];
    const float* wt = (const float*)d_in[1];
    float* out      = (float*)d_out;

    static cudaStream_t sB = []() {
        cudaStream_t s;
        cudaStreamCreateWithFlags(&s, cudaStreamNonBlocking);
        return s;
    }();
    static cudaEvent_t evFork = []() {
        cudaEvent_t e;
        cudaEventCreateWithFlags(&e, cudaEventDisableTiming);
        return e;
    }();
    static cudaEvent_t evJoin = []() {
        cudaEvent_t e;
        cudaEventCreateWithFlags(&e, cudaEventDisableTiming);
        return e;
    }();

    // Fork second stream into the captured graph.
    cudaEventRecord(evFork, 0);
    cudaStreamWaitEvent(sB, evFork, 0);

    // Even chunks on capture stream, odd chunks on sB.
    for (int b = 0; b < NCHNK; b++) {
        cudaStream_t s = (b & 1) ? sB : (cudaStream_t)0;
        reduce_kernel<<<R_BLK, 256, 0, s>>>(x, b);
        conv_kernel<<<C_BLK, 256, 0, s>>>(wt, b);
        mul_kernel<<<M_BLK, 256, 0, s>>>(x, out, b);
    }

    // Join.
    cudaEventRecord(evJoin, sB);
    cudaStreamWaitEvent(0, evJoin, 0);
}

// round 17
// speedup vs baseline: 1.7372x; 1.2156x over previous
#include <cuda_runtime.h>
#include <math_constants.h>

// SpatialAttention: out = x * hardsigmoid(conv3x3([mean_c(x); max_c(x)]))
// x: [16, 256, 128, 128] fp32, conv_w: [1, 2, 3, 3] fp32.
//
// FOUR-STREAM pipeline. Solo reduce is pinned at ~2.4 TB/s (9 variants:
// shape/occupancy/cp.async all falsified as fixes) while mul runs 4.3+
// TB/s. So run 4 chunks' chains CONCURRENTLY: aggregate DRAM demand from
// 4 independent phase kernels saturates HBM even though each is slow solo.
// Chunk b -> stream b%4; chain within a stream is ordered; fork/join via
// events (capturable).

#define BATCH 16
#define CH    256
#define HH    128
#define WW    128
#define HWSZ  (HH * WW)          // 16384
#define HW4   (HWSZ / 4)         // 4096 float4 cols per (b,c) plane
#define NCHNK 16                 // 1 batch per chunk (16 MiB x-slice)
#define NSTREAM 4

#define COLS_PER_BLK 16
#define RTHREADS 512
#define NGRP  (RTHREADS / COLS_PER_BLK)   // 32 channel groups
#define CPS   (CH / NGRP)                 // 8 channels per group

#define R_BLK 256                // reduce blocks per chunk
#define C_BLK 64                 // conv blocks per chunk
#define M_BLK 4096               // mul blocks per chunk

__device__ float g_avg[BATCH * HWSZ];
__device__ float g_max[BATCH * HWSZ];
__device__ float g_att[BATCH * HWSZ];

// ---------------------------------------------------------------------------
__global__ void __launch_bounds__(RTHREADS) reduce_kernel(const float* __restrict__ x, int b) {
    __shared__ float4 ssum[RTHREADS];
    __shared__ float4 smax[RTHREADS];

    int t       = threadIdx.x;
    int colBase = blockIdx.x * COLS_PER_BLK;
    int col_l   = t & (COLS_PER_BLK - 1);
    int cg      = t >> 4;                 // 0..31 channel group

    const float4* xp = reinterpret_cast<const float4*>(x)
                     + (size_t)b * CH * HW4 + (size_t)cg * CPS * HW4
                     + colBase + col_l;

    float4 s = make_float4(0.f, 0.f, 0.f, 0.f);
    float4 m = make_float4(-CUDART_INF_F, -CUDART_INF_F, -CUDART_INF_F, -CUDART_INF_F);

    #pragma unroll
    for (int c = 0; c < CPS; c++) {
        float4 v = xp[c * HW4];
        s.x += v.x; s.y += v.y; s.z += v.z; s.w += v.w;
        m.x = fmaxf(m.x, v.x); m.y = fmaxf(m.y, v.y);
        m.z = fmaxf(m.z, v.z); m.w = fmaxf(m.w, v.w);
    }
    ssum[t] = s; smax[t] = m;
    __syncthreads();

    #pragma unroll
    for (int off = RTHREADS / 2; off >= COLS_PER_BLK; off >>= 1) {
        if (t < off) {
            float4 s2 = ssum[t + off], m2 = smax[t + off];
            float4 sa = ssum[t],       ma = smax[t];
            sa.x += s2.x; sa.y += s2.y; sa.z += s2.z; sa.w += s2.w;
            ma.x = fmaxf(ma.x, m2.x); ma.y = fmaxf(ma.y, m2.y);
            ma.z = fmaxf(ma.z, m2.z); ma.w = fmaxf(ma.w, m2.w);
            ssum[t] = sa; smax[t] = ma;
        }
        __syncthreads();
    }

    if (t < COLS_PER_BLK) {
        const float inv = 1.0f / (float)CH;
        float4 sa = ssum[t], ma = smax[t];
        float4 a = make_float4(sa.x * inv, sa.y * inv, sa.z * inv, sa.w * inv);
        reinterpret_cast<float4*>(g_avg)[b * HW4 + colBase + t] = a;
        reinterpret_cast<float4*>(g_max)[b * HW4 + colBase + t] = ma;
    }
}

// ---------------------------------------------------------------------------
__global__ void __launch_bounds__(256) conv_kernel(const float* __restrict__ wt, int b) {
    int idx = blockIdx.x * 256 + threadIdx.x;   // 0 .. HWSZ-1
    int h   = idx >> 7;
    int w   = idx & (WW - 1);

    const float* __restrict__ A = g_avg + b * HWSZ;
    const float* __restrict__ M = g_max + b * HWSZ;

    float acc = 0.f;
    #pragma unroll
    for (int kh = 0; kh < 3; kh++) {
        int hh = h + kh - 1;
        if (hh < 0 || hh >= HH) continue;
        #pragma unroll
        for (int kw = 0; kw < 3; kw++) {
            int ww = w + kw - 1;
            if (ww < 0 || ww >= WW) continue;
            int o = hh * WW + ww;
            acc += __ldg(&wt[kh * 3 + kw])     * A[o]
                 + __ldg(&wt[9 + kh * 3 + kw]) * M[o];
        }
    }
    float y = fminf(fmaxf(acc + 3.0f, 0.0f), 6.0f) * (1.0f / 6.0f);
    g_att[b * HWSZ + idx] = y;
}

// ---------------------------------------------------------------------------
__global__ void __launch_bounds__(256) mul_kernel(const float* __restrict__ x,
                                                  float* __restrict__ out, int b) {
    int idx = blockIdx.x * 256 + threadIdx.x;   // 0 .. CH*HW4-1
    int col = idx & (HW4 - 1);

    size_t gidx = (size_t)b * CH * HW4 + idx;

    float4 v = __ldcs(reinterpret_cast<const float4*>(x) + gidx);
    float4 a = __ldg(reinterpret_cast<const float4*>(g_att) + (size_t)b * HW4 + col);

    v.x *= a.x; v.y *= a.y; v.z *= a.z; v.w *= a.w;
    __stcs(reinterpret_cast<float4*>(out) + gidx, v);
}

// ---------------------------------------------------------------------------
extern "C" void kernel_launch(void* const* d_in, const int* in_sizes, int n_in,
                              void* d_out, int out_size) {
    const float* x  = (const float*)d_in[0];
    const float* wt = (const float*)d_in[1];
    float* out      = (float*)d_out;

    static cudaStream_t streams[NSTREAM - 1];
    static cudaEvent_t  evFork;
    static cudaEvent_t  evJoin[NSTREAM - 1];
    static bool init = false;
    if (!init) {
        for (int i = 0; i < NSTREAM - 1; i++) {
            cudaStreamCreateWithFlags(&streams[i], cudaStreamNonBlocking);
            cudaEventCreateWithFlags(&evJoin[i], cudaEventDisableTiming);
        }
        cudaEventCreateWithFlags(&evFork, cudaEventDisableTiming);
        init = true;
    }

    // Fork the extra streams into the captured graph.
    cudaEventRecord(evFork, 0);
    for (int i = 0; i < NSTREAM - 1; i++)
        cudaStreamWaitEvent(streams[i], evFork, 0);

    // Chunk b -> stream b % NSTREAM (stream 0 = capture stream).
    for (int b = 0; b < NCHNK; b++) {
        int si = b % NSTREAM;
        cudaStream_t s = (si == 0) ? (cudaStream_t)0 : streams[si - 1];
        reduce_kernel<<<R_BLK, RTHREADS, 0, s>>>(x, b);
        conv_kernel<<<C_BLK, 256, 0, s>>>(wt, b);
        mul_kernel<<<M_BLK, 256, 0, s>>>(x, out, b);
    }

    // Join all extra streams back into the capture stream.
    for (int i = 0; i < NSTREAM - 1; i++) {
        cudaEventRecord(evJoin[i], streams[i]);
        cudaStreamWaitEvent(0, evJoin[i], 0);
    }
}